// round 4
// baseline (speedup 1.0000x reference)
#include <cuda_runtime.h>
#include <math.h>

#define T_TOK 6304
#define DMODEL 768
#define HDIM 768
#define NEXP 16
#define TM 64
#define TN 64
#define TK 16
#define MAX_TILES 128
#define SPAD 4   // smem padding (floats) to reduce bank conflicts

// ---------------- scratch (device globals; no allocations allowed) ----------
__device__ float g_hidden[T_TOK * HDIM];          // sorted-row hidden activations
__device__ int   g_idx[T_TOK];
__device__ int   g_counts[NEXP];
__device__ int   g_off[NEXP + 1];
__device__ int   g_cursor[NEXP];
__device__ int   g_perm[T_TOK];                   // sorted pos -> token id
__device__ int   g_tile_e[MAX_TILES];
__device__ int   g_tile_row[MAX_TILES];

// ---------------- init: zero per-launch state --------------------------------
__global__ void init_kernel() {
    int t = threadIdx.x;
    if (t < NEXP) g_counts[t] = 0;
}

// ---------------- gate: logits + argmax + counts -----------------------------
// 256 threads = 8 warps, one token per warp; Wg staged in smem (48 KB).
__global__ void gate_kernel(const float* __restrict__ x,
                            const float* __restrict__ Wg,
                            const float* __restrict__ bg) {
    __shared__ float wgs[NEXP * DMODEL];   // 49152 B
    int tid = threadIdx.x;
    for (int i = tid; i < NEXP * DMODEL; i += 256) wgs[i] = Wg[i];
    __syncthreads();

    int w = tid >> 5, l = tid & 31;
    int t = blockIdx.x * 8 + w;
    if (t >= T_TOK) return;

    const float* xr = x + (size_t)t * DMODEL;
    float best = -1e30f; int bi = 0;
    #pragma unroll 1
    for (int e = 0; e < NEXP; e++) {
        float s = 0.f;
        const float* wr = wgs + e * DMODEL;
        for (int k = l; k < DMODEL; k += 32) s += xr[k] * wr[k];
        #pragma unroll
        for (int o = 16; o; o >>= 1) s += __shfl_xor_sync(0xffffffffu, s, o);
        s += bg[e];
        if (s > best) { best = s; bi = e; }   // strict > : first max (jnp.argmax)
    }
    if (l == 0) {
        g_idx[t] = bi;
        atomicAdd(&g_counts[bi], 1);
    }
}

// ---------------- scan: offsets, cursors, tile list (serial, trivial) --------
__global__ void scan_kernel() {
    if (threadIdx.x != 0) return;
    int off = 0, nt = 0;
    for (int e = 0; e < NEXP; e++) {
        g_off[e] = off;
        g_cursor[e] = off;
        int c = g_counts[e];
        for (int r = 0; r < c; r += TM) {
            g_tile_e[nt] = e;
            g_tile_row[nt] = off + r;
            nt++;
        }
        off += c;
    }
    g_off[NEXP] = off;
    for (; nt < MAX_TILES; nt++) g_tile_e[nt] = -1;
}

// ---------------- scatter: build perm ----------------------------------------
__global__ void scatter_kernel() {
    int t = blockIdx.x * 256 + threadIdx.x;
    if (t >= T_TOK) return;
    int e = g_idx[t];
    int p = atomicAdd(&g_cursor[e], 1);
    g_perm[p] = t;
}

// ---------------- grouped GEMM core ------------------------------------------
// PHASE 1: hidden[sorted_r, :] = GELU( x[perm[r]] @ W1[e]^T + b1[e] )
// PHASE 2: out[perm[r], :]     =       hidden[r]  @ W2[e]^T + b2[e]
// Tile: 64 rows (tokens of one expert) x 64 cols, K staged 16 at a time.
template <int PHASE>
__global__ void __launch_bounds__(256)
mlp_gemm(const float* __restrict__ x,      // PHASE1: tokens; PHASE2: unused
         const float* __restrict__ W,      // [E, out_dim(768), k_dim(768)]
         const float* __restrict__ bias,   // [E, out_dim]
         float* __restrict__ out)          // PHASE2 only
{
    int tile = blockIdx.x;
    int e = g_tile_e[tile];
    if (e < 0) return;
    int row0 = g_tile_row[tile];
    int rend = g_off[e + 1];
    int n0 = blockIdx.y * TN;

    __shared__ float As[TK][TM + SPAD];
    __shared__ float Bs[TK][TN + SPAD];

    int tid = threadIdx.x;
    int tx = tid & 15, ty = tid >> 4;

    // loader mapping: 256 threads -> 64 rows x 4 float4 k-chunks
    int lm = tid >> 2;
    int lk = (tid & 3) * 4;

    int arow = row0 + lm;
    bool avalid = arow < rend;
    const float* aptr;
    if (PHASE == 1) {
        int tok = avalid ? g_perm[arow] : 0;
        aptr = x + (size_t)tok * DMODEL;
    } else {
        aptr = g_hidden + (size_t)arow * HDIM;     // sorted rows: contiguous
    }
    const float* bptr = W + (size_t)e * HDIM * DMODEL + (size_t)(n0 + lm) * DMODEL;

    float acc[4][4];
    #pragma unroll
    for (int i = 0; i < 4; i++)
        #pragma unroll
        for (int j = 0; j < 4; j++) acc[i][j] = 0.f;

    for (int k0 = 0; k0 < DMODEL; k0 += TK) {
        float4 av = avalid ? *(const float4*)(aptr + k0 + lk)
                           : make_float4(0.f, 0.f, 0.f, 0.f);
        float4 bv = *(const float4*)(bptr + k0 + lk);
        __syncthreads();
        As[lk + 0][lm] = av.x; As[lk + 1][lm] = av.y;
        As[lk + 2][lm] = av.z; As[lk + 3][lm] = av.w;
        Bs[lk + 0][lm] = bv.x; Bs[lk + 1][lm] = bv.y;
        Bs[lk + 2][lm] = bv.z; Bs[lk + 3][lm] = bv.w;
        __syncthreads();
        #pragma unroll
        for (int k = 0; k < TK; k++) {
            float4 a4 = *(const float4*)&As[k][ty * 4];
            float4 b4 = *(const float4*)&Bs[k][tx * 4];
            float a[4] = {a4.x, a4.y, a4.z, a4.w};
            float b[4] = {b4.x, b4.y, b4.z, b4.w};
            #pragma unroll
            for (int i = 0; i < 4; i++)
                #pragma unroll
                for (int j = 0; j < 4; j++)
                    acc[i][j] += a[i] * b[j];
        }
    }

    // epilogue
    #pragma unroll
    for (int i = 0; i < 4; i++) {
        int r = row0 + ty * 4 + i;
        if (r >= rend) continue;
        if (PHASE == 1) {
            float* hr = g_hidden + (size_t)r * HDIM + n0;
            #pragma unroll
            for (int j = 0; j < 4; j++) {
                int n = tx * 4 + j;
                float v = acc[i][j] + bias[e * HDIM + n0 + n];
                // exact GELU: 0.5*v*(1+erf(v/sqrt(2)))
                hr[n] = 0.5f * v * (1.0f + erff(v * 0.70710678118654752f));
            }
        } else {
            int tok = g_perm[r];
            float* orow = out + (size_t)tok * DMODEL + n0;
            #pragma unroll
            for (int j = 0; j < 4; j++) {
                int n = tx * 4 + j;
                orow[n] = acc[i][j] + bias[e * DMODEL + n0 + n];
            }
        }
    }
}

// ---------------- launch -----------------------------------------------------
extern "C" void kernel_launch(void* const* d_in, const int* in_sizes, int n_in,
                              void* d_out, int out_size) {
    const float* x  = (const float*)d_in[0];
    const float* W1 = (const float*)d_in[1];
    const float* b1 = (const float*)d_in[2];
    const float* W2 = (const float*)d_in[3];
    const float* b2 = (const float*)d_in[4];
    const float* Wg = (const float*)d_in[5];
    const float* bg = (const float*)d_in[6];
    float* out = (float*)d_out;

    init_kernel<<<1, 32>>>();
    gate_kernel<<<(T_TOK + 7) / 8, 256>>>(x, Wg, bg);
    scan_kernel<<<1, 1>>>();
    scatter_kernel<<<(T_TOK + 255) / 256, 256>>>();

    dim3 g(MAX_TILES, HDIM / TN);
    mlp_gemm<1><<<g, 256>>>(x, W1, b1, nullptr);
    mlp_gemm<2><<<g, 256>>>(nullptr, W2, b2, out);
}

// round 6
// speedup vs baseline: 1.7276x; 1.7276x over previous
#include <cuda_runtime.h>
#include <cstdint>
#include <math.h>

#define T_TOK 6304
#define DMODEL 768
#define NEXP 16
#define TM 128
#define TN 128
#define KSTEP 32
#define NSTAGE (DMODEL / KSTEP)      // 24
#define MAX_TILES 128

#define ASTRIDE 36                   // floats per smem tile row (pad 32 -> 36)
#define ATILE (128 * ASTRIDE)        // floats per A/B tile buffer (4608)
#define STG_STRIDE 136               // epilogue staging row stride (floats)
#define SMEM_BYTES (2048 + 4 * ATILE * 4)   // head(bias) + A0,A1,B0,B1

// ---------------- scratch (device globals; no allocations allowed) ----------
__device__ float g_hidden[T_TOK * DMODEL];
__device__ int   g_idx[T_TOK];
__device__ int   g_counts[NEXP];
__device__ int   g_off[NEXP + 1];
__device__ int   g_cursor[NEXP];
__device__ int   g_perm[T_TOK];
__device__ int   g_tile_e[MAX_TILES];
__device__ int   g_tile_row[MAX_TILES];

// ---------------- helpers ----------------------------------------------------
__device__ __forceinline__ uint32_t f2tf32(float f) {
    uint32_t u;
    asm("cvt.rna.tf32.f32 %0, %1;" : "=r"(u) : "f"(f));
    return u;
}
__device__ __forceinline__ uint4 cvt4(float4 v) {
    return make_uint4(f2tf32(v.x), f2tf32(v.y), f2tf32(v.z), f2tf32(v.w));
}
__device__ __forceinline__ void mma_tf32(float* c, const uint32_t* a, const uint32_t* b) {
    asm volatile(
        "mma.sync.aligned.m16n8k8.row.col.f32.tf32.tf32.f32 "
        "{%0,%1,%2,%3}, {%4,%5,%6,%7}, {%8,%9}, {%0,%1,%2,%3};"
        : "+f"(c[0]), "+f"(c[1]), "+f"(c[2]), "+f"(c[3])
        : "r"(a[0]), "r"(a[1]), "r"(a[2]), "r"(a[3]), "r"(b[0]), "r"(b[1]));
}

// ---------------- small kernels (unchanged logic) ----------------------------
__global__ void init_kernel() {
    int t = threadIdx.x;
    if (t < NEXP) g_counts[t] = 0;
}

__global__ void gate_kernel(const float* __restrict__ x,
                            const float* __restrict__ Wg,
                            const float* __restrict__ bg) {
    __shared__ float wgs[NEXP * DMODEL];
    int tid = threadIdx.x;
    for (int i = tid; i < NEXP * DMODEL; i += 256) wgs[i] = Wg[i];
    __syncthreads();
    int w = tid >> 5, l = tid & 31;
    int t = blockIdx.x * 8 + w;
    if (t >= T_TOK) return;
    const float* xr = x + (size_t)t * DMODEL;
    float best = -1e30f; int bi = 0;
    #pragma unroll 1
    for (int e = 0; e < NEXP; e++) {
        float s = 0.f;
        const float* wr = wgs + e * DMODEL;
        for (int k = l; k < DMODEL; k += 32) s += xr[k] * wr[k];
        #pragma unroll
        for (int o = 16; o; o >>= 1) s += __shfl_xor_sync(0xffffffffu, s, o);
        s += bg[e];
        if (s > best) { best = s; bi = e; }   // strict > : first max (jnp.argmax)
    }
    if (l == 0) { g_idx[t] = bi; atomicAdd(&g_counts[bi], 1); }
}

__global__ void scan_kernel() {
    if (threadIdx.x != 0) return;
    int off = 0, nt = 0;
    for (int e = 0; e < NEXP; e++) {
        g_off[e] = off;
        g_cursor[e] = off;
        int c = g_counts[e];
        for (int r = 0; r < c; r += TM) { g_tile_e[nt] = e; g_tile_row[nt] = off + r; nt++; }
        off += c;
    }
    g_off[NEXP] = off;
    for (; nt < MAX_TILES; nt++) g_tile_e[nt] = -1;
}

__global__ void scatter_kernel() {
    int t = blockIdx.x * 256 + threadIdx.x;
    if (t >= T_TOK) return;
    int p = atomicAdd(&g_cursor[g_idx[t]], 1);
    g_perm[p] = t;
}

// ---------------- tf32 mma.sync grouped GEMM ---------------------------------
// PHASE 1: hidden[r,:] = GELU(x[perm[r]] @ W1[e]^T + b1[e])
// PHASE 2: out[perm[r],:] = hidden[r] @ W2[e]^T + b2[e]
template <int PHASE>
__global__ void __launch_bounds__(256, 1)
mlp_mma(const float* __restrict__ x, const float* __restrict__ W,
        const float* __restrict__ bias, float* __restrict__ out)
{
    int tile = blockIdx.x;
    int e = g_tile_e[tile];
    if (e < 0) return;
    int row0 = g_tile_row[tile];
    int rend = g_off[e + 1];
    int n0 = blockIdx.y * TN;

    extern __shared__ char sm[];
    float* bias_s = (float*)(sm);                 // 512 B
    float* smf = (float*)(sm + 2048);             // tile buffers (16B aligned)

    int tid = threadIdx.x;
    int wid = tid >> 5, lane = tid & 31;
    int wr = wid & 3, wc = wid >> 2;              // warp tile: rows wr*32, cols wc*64
    int lrow = lane >> 2, lcol = lane & 3;        // quad decomposition
    int rowp = tid >> 1, side = tid & 1;          // loader: 2 threads per tile row

    if (tid < TN) bias_s[tid] = bias[(size_t)e * DMODEL + n0 + tid];

    // per-thread source rows (fixed across K stages)
    int arow = row0 + rowp;
    bool avalid = arow < rend;
    const float* aptr;
    if (PHASE == 1) {
        int tok = avalid ? g_perm[arow] : 0;
        aptr = x + (size_t)tok * DMODEL;
    } else {
        aptr = g_hidden + (size_t)(avalid ? arow : 0) * DMODEL;
    }
    const float* bptr = W + (size_t)e * DMODEL * DMODEL + (size_t)(n0 + rowp) * DMODEL;

    float acc[2][8][4];
    #pragma unroll
    for (int mm = 0; mm < 2; mm++)
        #pragma unroll
        for (int nn = 0; nn < 8; nn++)
            #pragma unroll
            for (int j = 0; j < 4; j++) acc[mm][nn][j] = 0.f;

    // ---- prologue: stage 0 -> smem buf0; stage 1 -> regs R ----
    float4 ra[4], rb[4];
    {
        #pragma unroll
        for (int q = 0; q < 4; q++) {
            int col = side * 16 + q * 4;
            float4 av = avalid ? *(const float4*)(aptr + col) : make_float4(0, 0, 0, 0);
            float4 bv = *(const float4*)(bptr + col);
            *(uint4*)(smf + 0 * ATILE + rowp * ASTRIDE + col) = cvt4(av);
            *(uint4*)(smf + 2 * ATILE + rowp * ASTRIDE + col) = cvt4(bv);
        }
        #pragma unroll
        for (int q = 0; q < 4; q++) {
            int col = KSTEP + side * 16 + q * 4;
            ra[q] = avalid ? *(const float4*)(aptr + col) : make_float4(0, 0, 0, 0);
            rb[q] = *(const float4*)(bptr + col);
        }
    }
    __syncthreads();

    // ---- mainloop ----
    #pragma unroll 1
    for (int s = 0; s < NSTAGE; s++) {
        int buf = s & 1;
        // store stage s+1 (held in R) into the other buffer
        if (s + 1 < NSTAGE) {
            float* dA = smf + (buf ^ 1) * ATILE + rowp * ASTRIDE + side * 16;
            float* dB = smf + (2 + (buf ^ 1)) * ATILE + rowp * ASTRIDE + side * 16;
            #pragma unroll
            for (int q = 0; q < 4; q++) {
                *(uint4*)(dA + q * 4) = cvt4(ra[q]);
                *(uint4*)(dB + q * 4) = cvt4(rb[q]);
            }
        }
        // prefetch stage s+2 into R (latency overlapped with compute)
        if (s + 2 < NSTAGE) {
            int k0 = (s + 2) * KSTEP + side * 16;
            #pragma unroll
            for (int q = 0; q < 4; q++) {
                ra[q] = avalid ? *(const float4*)(aptr + k0 + q * 4) : make_float4(0, 0, 0, 0);
                rb[q] = *(const float4*)(bptr + k0 + q * 4);
            }
        }
        // compute stage s
        const float* A = smf + buf * ATILE;
        const float* B = smf + (2 + buf) * ATILE;
        #pragma unroll
        for (int kk = 0; kk < 4; kk++) {
            int k0 = kk * 8;
            uint32_t af[2][4];
            #pragma unroll
            for (int mm = 0; mm < 2; mm++) {
                const float* a = A + (wr * 32 + mm * 16 + lrow) * ASTRIDE + k0 + lcol;
                af[mm][0] = __float_as_uint(a[0]);
                af[mm][1] = __float_as_uint(a[8 * ASTRIDE]);
                af[mm][2] = __float_as_uint(a[4]);
                af[mm][3] = __float_as_uint(a[8 * ASTRIDE + 4]);
            }
            #pragma unroll
            for (int nn = 0; nn < 8; nn++) {
                const float* bp = B + (wc * 64 + nn * 8 + lrow) * ASTRIDE + k0 + lcol;
                uint32_t bf[2];
                bf[0] = __float_as_uint(bp[0]);
                bf[1] = __float_as_uint(bp[4]);
                mma_tf32(acc[0][nn], af[0], bf);
                mma_tf32(acc[1][nn], af[1], bf);
            }
        }
        __syncthreads();
    }

    // ---- epilogue: acc -> bias/GELU -> smem staging -> coalesced gmem ----
    {
        float* stg = smf;    // reuse tile buffers (128 x STG_STRIDE floats)
        #pragma unroll
        for (int mm = 0; mm < 2; mm++) {
            #pragma unroll
            for (int nn = 0; nn < 8; nn++) {
                int col = wc * 64 + nn * 8 + 2 * lcol;
                int row = wr * 32 + mm * 16 + lrow;
                float b0 = bias_s[col], b1 = bias_s[col + 1];
                float v0 = acc[mm][nn][0] + b0, v1 = acc[mm][nn][1] + b1;
                float v2 = acc[mm][nn][2] + b0, v3 = acc[mm][nn][3] + b1;
                if (PHASE == 1) {
                    v0 = 0.5f * v0 * (1.0f + erff(v0 * 0.70710678118654752f));
                    v1 = 0.5f * v1 * (1.0f + erff(v1 * 0.70710678118654752f));
                    v2 = 0.5f * v2 * (1.0f + erff(v2 * 0.70710678118654752f));
                    v3 = 0.5f * v3 * (1.0f + erff(v3 * 0.70710678118654752f));
                }
                *(float2*)(stg + row * STG_STRIDE + col) = make_float2(v0, v1);
                *(float2*)(stg + (row + 8) * STG_STRIDE + col) = make_float2(v2, v3);
            }
        }
    }
    __syncthreads();

    // coalesced writeout: 2 threads per row, 16 float4 each
    {
        int r = rowp;
        int gr = row0 + r;
        if (gr < rend) {
            float* dst;
            if (PHASE == 1) dst = g_hidden + (size_t)gr * DMODEL + n0;
            else            dst = out + (size_t)g_perm[gr] * DMODEL + n0;
            const float* srow = smf + r * STG_STRIDE + side * 64;
            #pragma unroll
            for (int j = 0; j < 16; j++)
                *(float4*)(dst + side * 64 + j * 4) = *(const float4*)(srow + j * 4);
        }
    }
}

// ---------------- launch -----------------------------------------------------
extern "C" void kernel_launch(void* const* d_in, const int* in_sizes, int n_in,
                              void* d_out, int out_size) {
    const float* x  = (const float*)d_in[0];
    const float* W1 = (const float*)d_in[1];
    const float* b1 = (const float*)d_in[2];
    const float* W2 = (const float*)d_in[3];
    const float* b2 = (const float*)d_in[4];
    const float* Wg = (const float*)d_in[5];
    const float* bg = (const float*)d_in[6];
    float* out = (float*)d_out;

    cudaFuncSetAttribute(mlp_mma<1>, cudaFuncAttributeMaxDynamicSharedMemorySize, SMEM_BYTES);
    cudaFuncSetAttribute(mlp_mma<2>, cudaFuncAttributeMaxDynamicSharedMemorySize, SMEM_BYTES);

    init_kernel<<<1, 32>>>();
    gate_kernel<<<(T_TOK + 7) / 8, 256>>>(x, Wg, bg);
    scan_kernel<<<1, 1>>>();
    scatter_kernel<<<(T_TOK + 255) / 256, 256>>>();

    dim3 g(MAX_TILES, DMODEL / TN);
    mlp_mma<1><<<g, 256, SMEM_BYTES>>>(x, W1, b1, nullptr);
    mlp_mma<2><<<g, 256, SMEM_BYTES>>>(nullptr, W2, b2, out);
}

// round 7
// speedup vs baseline: 2.5993x; 1.5046x over previous
#include <cuda_runtime.h>
#include <cuda_fp16.h>
#include <cstdint>
#include <math.h>

#define T_TOK 6304
#define DMODEL 768
#define NEXP 16
#define TM 128
#define TN 128
#define KSTEP 32
#define NSTAGE (DMODEL / KSTEP)      // 24
#define MAX_TILES 128

#define HSTRIDE 40                   // halfs per smem tile row (pad 32 -> 40)
#define TILEH (128 * HSTRIDE)        // halfs per tile buffer
#define STG_STRIDE 136               // epilogue staging row stride (floats)
#define SMEM_BYTES (2048 + 128 * STG_STRIDE * 4)   // staging dominates (tiles fit inside)

// ---------------- scratch (device globals; no allocations allowed) ----------
__device__ float g_hidden[T_TOK * DMODEL];
__device__ int   g_idx[T_TOK];
__device__ int   g_counts[NEXP];
__device__ int   g_off[NEXP + 1];
__device__ int   g_cursor[NEXP];
__device__ int   g_perm[T_TOK];
__device__ int   g_tile_e[MAX_TILES];
__device__ int   g_tile_row[MAX_TILES];

// ---------------- helpers ----------------------------------------------------
__device__ __forceinline__ uint2 f4_to_h4(float4 v) {
    __half2 lo = __floats2half2_rn(v.x, v.y);
    __half2 hi = __floats2half2_rn(v.z, v.w);
    return make_uint2(*(uint32_t*)&lo, *(uint32_t*)&hi);
}
__device__ __forceinline__ void ldsm4(uint32_t* r, uint32_t addr) {
    asm volatile("ldmatrix.sync.aligned.m8n8.x4.shared.b16 {%0,%1,%2,%3}, [%4];"
                 : "=r"(r[0]), "=r"(r[1]), "=r"(r[2]), "=r"(r[3]) : "r"(addr));
}
__device__ __forceinline__ void mma_f16(float* c, const uint32_t* a, const uint32_t* b) {
    asm volatile(
        "mma.sync.aligned.m16n8k16.row.col.f32.f16.f16.f32 "
        "{%0,%1,%2,%3}, {%4,%5,%6,%7}, {%8,%9}, {%0,%1,%2,%3};"
        : "+f"(c[0]), "+f"(c[1]), "+f"(c[2]), "+f"(c[3])
        : "r"(a[0]), "r"(a[1]), "r"(a[2]), "r"(a[3]), "r"(b[0]), "r"(b[1]));
}

// ---------------- small kernels (unchanged logic) ----------------------------
__global__ void init_kernel() {
    int t = threadIdx.x;
    if (t < NEXP) g_counts[t] = 0;
}

__global__ void gate_kernel(const float* __restrict__ x,
                            const float* __restrict__ Wg,
                            const float* __restrict__ bg) {
    __shared__ float wgs[NEXP * DMODEL];
    int tid = threadIdx.x;
    for (int i = tid; i < NEXP * DMODEL; i += 256) wgs[i] = Wg[i];
    __syncthreads();
    int w = tid >> 5, l = tid & 31;
    int t = blockIdx.x * 8 + w;
    if (t >= T_TOK) return;
    const float* xr = x + (size_t)t * DMODEL;
    float best = -1e30f; int bi = 0;
    #pragma unroll 1
    for (int e = 0; e < NEXP; e++) {
        float s = 0.f;
        const float* wr = wgs + e * DMODEL;
        for (int k = l; k < DMODEL; k += 32) s += xr[k] * wr[k];
        #pragma unroll
        for (int o = 16; o; o >>= 1) s += __shfl_xor_sync(0xffffffffu, s, o);
        s += bg[e];
        if (s > best) { best = s; bi = e; }   // strict > : first max (jnp.argmax)
    }
    if (l == 0) { g_idx[t] = bi; atomicAdd(&g_counts[bi], 1); }
}

__global__ void scan_kernel() {
    if (threadIdx.x != 0) return;
    int off = 0, nt = 0;
    for (int e = 0; e < NEXP; e++) {
        g_off[e] = off;
        g_cursor[e] = off;
        int c = g_counts[e];
        for (int r = 0; r < c; r += TM) { g_tile_e[nt] = e; g_tile_row[nt] = off + r; nt++; }
        off += c;
    }
    g_off[NEXP] = off;
    for (; nt < MAX_TILES; nt++) g_tile_e[nt] = -1;
}

__global__ void scatter_kernel() {
    int t = blockIdx.x * 256 + threadIdx.x;
    if (t >= T_TOK) return;
    int p = atomicAdd(&g_cursor[g_idx[t]], 1);
    g_perm[p] = t;
}

// ---------------- fp16 mma.sync grouped GEMM (ldmatrix operand path) ---------
// PHASE 1: hidden[r,:] = GELU(x[perm[r]] @ W1[e]^T + b1[e])
// PHASE 2: out[perm[r],:] = hidden[r] @ W2[e]^T + b2[e]
template <int PHASE>
__global__ void __launch_bounds__(256, 1)
mlp_mma(const float* __restrict__ x, const float* __restrict__ W,
        const float* __restrict__ bias, float* __restrict__ out)
{
    int tile = blockIdx.x;
    int e = g_tile_e[tile];
    if (e < 0) return;
    int row0 = g_tile_row[tile];
    int rend = g_off[e + 1];
    int n0 = blockIdx.y * TN;

    extern __shared__ char sm[];
    float* bias_s = (float*)(sm);                 // 512 B
    __half* tiles = (__half*)(sm + 2048);         // A0,A1,B0,B1 (10240 B each)
    float* smf = (float*)(sm + 2048);             // epilogue staging alias

    int tid = threadIdx.x;
    int wid = tid >> 5, lane = tid & 31;
    int wr = wid & 3, wc = wid >> 2;              // warp tile: rows wr*32, cols wc*64
    int lrow = lane >> 2, lcol = lane & 3;        // quad decomposition (epilogue)
    int rowp = tid >> 1, side = tid & 1;          // loader: 2 threads per tile row

    if (tid < TN) bias_s[tid] = bias[(size_t)e * DMODEL + n0 + tid];

    // ldmatrix lane address components
    int lq = lane >> 3, lr = lane & 7;
    int a_row_base = wr * 32 + (lq & 1) * 8 + lr;     // + mm*16
    int a_col_base = (lq >> 1) * 8;                   // + kk*16
    int b_row_base = wc * 64 + (lq >> 1) * 8 + lr;    // + np*16
    int b_col_base = (lq & 1) * 8;                    // + kk*16

    // per-thread source rows (fixed across K stages)
    int arow = row0 + rowp;
    bool avalid = arow < rend;
    const float* aptr;
    if (PHASE == 1) {
        int tok = avalid ? g_perm[arow] : 0;
        aptr = x + (size_t)tok * DMODEL;
    } else {
        aptr = g_hidden + (size_t)(avalid ? arow : 0) * DMODEL;
    }
    const float* bptr = W + (size_t)e * DMODEL * DMODEL + (size_t)(n0 + rowp) * DMODEL;

    float acc[2][8][4];
    #pragma unroll
    for (int mm = 0; mm < 2; mm++)
        #pragma unroll
        for (int nn = 0; nn < 8; nn++)
            #pragma unroll
            for (int j = 0; j < 4; j++) acc[mm][nn][j] = 0.f;

    // ---- prologue: stage 0 -> smem buf0; stage 1 -> regs R ----
    float4 ra[4], rb[4];
    {
        __half* dA = tiles + 0 * TILEH + rowp * HSTRIDE + side * 16;
        __half* dB = tiles + 2 * TILEH + rowp * HSTRIDE + side * 16;
        #pragma unroll
        for (int q = 0; q < 4; q++) {
            int col = side * 16 + q * 4;
            float4 av = avalid ? *(const float4*)(aptr + col) : make_float4(0, 0, 0, 0);
            float4 bv = *(const float4*)(bptr + col);
            *(uint2*)(dA + q * 4) = f4_to_h4(av);
            *(uint2*)(dB + q * 4) = f4_to_h4(bv);
        }
        #pragma unroll
        for (int q = 0; q < 4; q++) {
            int col = KSTEP + side * 16 + q * 4;
            ra[q] = avalid ? *(const float4*)(aptr + col) : make_float4(0, 0, 0, 0);
            rb[q] = *(const float4*)(bptr + col);
        }
    }
    __syncthreads();

    // ---- mainloop ----
    #pragma unroll 1
    for (int s = 0; s < NSTAGE; s++) {
        int buf = s & 1;
        // store stage s+1 (held in R) into the other buffer
        if (s + 1 < NSTAGE) {
            __half* dA = tiles + (buf ^ 1) * TILEH + rowp * HSTRIDE + side * 16;
            __half* dB = tiles + (2 + (buf ^ 1)) * TILEH + rowp * HSTRIDE + side * 16;
            #pragma unroll
            for (int q = 0; q < 4; q++) {
                *(uint2*)(dA + q * 4) = f4_to_h4(ra[q]);
                *(uint2*)(dB + q * 4) = f4_to_h4(rb[q]);
            }
        }
        // prefetch stage s+2 into R (latency overlapped with compute)
        if (s + 2 < NSTAGE) {
            int k0 = (s + 2) * KSTEP + side * 16;
            #pragma unroll
            for (int q = 0; q < 4; q++) {
                ra[q] = avalid ? *(const float4*)(aptr + k0 + q * 4) : make_float4(0, 0, 0, 0);
                rb[q] = *(const float4*)(bptr + k0 + q * 4);
            }
        }
        // compute stage s: 2 k-chunks of 16
        const __half* A = tiles + buf * TILEH;
        const __half* B = tiles + (2 + buf) * TILEH;
        #pragma unroll
        for (int kk = 0; kk < 2; kk++) {
            uint32_t af[2][4];
            #pragma unroll
            for (int mm = 0; mm < 2; mm++) {
                const __half* p = A + (a_row_base + mm * 16) * HSTRIDE + a_col_base + kk * 16;
                ldsm4(af[mm], (uint32_t)__cvta_generic_to_shared(p));
            }
            uint32_t bf[4][4];   // bf[np] = {b0(nn=2np), b1(2np), b0(2np+1), b1(2np+1)}
            #pragma unroll
            for (int np = 0; np < 4; np++) {
                const __half* p = B + (b_row_base + np * 16) * HSTRIDE + b_col_base + kk * 16;
                ldsm4(bf[np], (uint32_t)__cvta_generic_to_shared(p));
            }
            #pragma unroll
            for (int np = 0; np < 4; np++) {
                mma_f16(acc[0][2 * np],     af[0], &bf[np][0]);
                mma_f16(acc[1][2 * np],     af[1], &bf[np][0]);
                mma_f16(acc[0][2 * np + 1], af[0], &bf[np][2]);
                mma_f16(acc[1][2 * np + 1], af[1], &bf[np][2]);
            }
        }
        __syncthreads();
    }

    // ---- epilogue: acc -> bias/GELU -> smem staging -> coalesced gmem ----
    {
        #pragma unroll
        for (int mm = 0; mm < 2; mm++) {
            #pragma unroll
            for (int nn = 0; nn < 8; nn++) {
                int col = wc * 64 + nn * 8 + 2 * lcol;
                int row = wr * 32 + mm * 16 + lrow;
                float b0 = bias_s[col], b1 = bias_s[col + 1];
                float v0 = acc[mm][nn][0] + b0, v1 = acc[mm][nn][1] + b1;
                float v2 = acc[mm][nn][2] + b0, v3 = acc[mm][nn][3] + b1;
                if (PHASE == 1) {
                    v0 = 0.5f * v0 * (1.0f + erff(v0 * 0.70710678118654752f));
                    v1 = 0.5f * v1 * (1.0f + erff(v1 * 0.70710678118654752f));
                    v2 = 0.5f * v2 * (1.0f + erff(v2 * 0.70710678118654752f));
                    v3 = 0.5f * v3 * (1.0f + erff(v3 * 0.70710678118654752f));
                }
                *(float2*)(smf + row * STG_STRIDE + col) = make_float2(v0, v1);
                *(float2*)(smf + (row + 8) * STG_STRIDE + col) = make_float2(v2, v3);
            }
        }
    }
    __syncthreads();

    // coalesced writeout: 2 threads per row, 16 float4 each
    {
        int r = rowp;
        int gr = row0 + r;
        if (gr < rend) {
            float* dst;
            if (PHASE == 1) dst = g_hidden + (size_t)gr * DMODEL + n0;
            else            dst = out + (size_t)g_perm[gr] * DMODEL + n0;
            const float* srow = smf + r * STG_STRIDE + side * 64;
            #pragma unroll
            for (int j = 0; j < 16; j++)
                *(float4*)(dst + side * 64 + j * 4) = *(const float4*)(srow + j * 4);
        }
    }
}

// ---------------- launch -----------------------------------------------------
extern "C" void kernel_launch(void* const* d_in, const int* in_sizes, int n_in,
                              void* d_out, int out_size) {
    const float* x  = (const float*)d_in[0];
    const float* W1 = (const float*)d_in[1];
    const float* b1 = (const float*)d_in[2];
    const float* W2 = (const float*)d_in[3];
    const float* b2 = (const float*)d_in[4];
    const float* Wg = (const float*)d_in[5];
    const float* bg = (const float*)d_in[6];
    float* out = (float*)d_out;

    cudaFuncSetAttribute(mlp_mma<1>, cudaFuncAttributeMaxDynamicSharedMemorySize, SMEM_BYTES);
    cudaFuncSetAttribute(mlp_mma<2>, cudaFuncAttributeMaxDynamicSharedMemorySize, SMEM_BYTES);

    init_kernel<<<1, 32>>>();
    gate_kernel<<<(T_TOK + 7) / 8, 256>>>(x, Wg, bg);
    scan_kernel<<<1, 1>>>();
    scatter_kernel<<<(T_TOK + 255) / 256, 256>>>();

    dim3 g(MAX_TILES, DMODEL / TN);
    mlp_mma<1><<<g, 256, SMEM_BYTES>>>(x, W1, b1, nullptr);
    mlp_mma<2><<<g, 256, SMEM_BYTES>>>(nullptr, W2, b2, out);
}

// round 8
// speedup vs baseline: 3.2002x; 1.2312x over previous
#include <cuda_runtime.h>
#include <cuda_fp16.h>
#include <cstdint>
#include <math.h>

#define T_TOK 6304
#define DMODEL 768
#define NEXP 16
#define TM 128
#define TN 128
#define KSTEP 32                     // halfs per stage
#define NSTAGE (DMODEL / KSTEP)      // 24
#define MAX_TILES 128

#define SLOT_B 8192                  // bytes per A (or B) stage slot: 128 rows x 64B
#define RING_OFF 2048
#define SMEM_BYTES (RING_OFF + 8 * SLOT_B)   // 67584: bias + 4-stage A ring + 4-stage B ring
#define STG_STRIDE 136               // epilogue staging row stride (floats), 64 rows per pass

// ---------------- scratch (device globals; no allocations allowed) ----------
__device__ __half g_xh[T_TOK * DMODEL];
__device__ __half g_w1h[NEXP * DMODEL * DMODEL];
__device__ __half g_w2h[NEXP * DMODEL * DMODEL];
__device__ __half g_hidden[T_TOK * DMODEL];
__device__ int    g_idx[T_TOK];
__device__ int    g_counts[NEXP];
__device__ int    g_off[NEXP + 1];
__device__ int    g_cursor[NEXP];
__device__ int    g_perm[T_TOK];
__device__ int    g_tile_e[MAX_TILES];
__device__ int    g_tile_row[MAX_TILES];

// ---------------- helpers ----------------------------------------------------
__device__ __forceinline__ void ldsm4(uint32_t* r, uint32_t addr) {
    asm volatile("ldmatrix.sync.aligned.m8n8.x4.shared.b16 {%0,%1,%2,%3}, [%4];"
                 : "=r"(r[0]), "=r"(r[1]), "=r"(r[2]), "=r"(r[3]) : "r"(addr));
}
__device__ __forceinline__ void mma_f16(float* c, const uint32_t* a, const uint32_t* b) {
    asm volatile(
        "mma.sync.aligned.m16n8k16.row.col.f32.f16.f16.f32 "
        "{%0,%1,%2,%3}, {%4,%5,%6,%7}, {%8,%9}, {%0,%1,%2,%3};"
        : "+f"(c[0]), "+f"(c[1]), "+f"(c[2]), "+f"(c[3])
        : "r"(a[0]), "r"(a[1]), "r"(a[2]), "r"(a[3]), "r"(b[0]), "r"(b[1]));
}
__device__ __forceinline__ void cpa16(uint32_t dst, const void* src, int srcsize) {
    asm volatile("cp.async.cg.shared.global [%0], [%1], 16, %2;"
                 :: "r"(dst), "l"(src), "r"(srcsize) : "memory");
}
#define CP_COMMIT() asm volatile("cp.async.commit_group;" ::: "memory")
#define CP_WAIT2()  asm volatile("cp.async.wait_group 2;" ::: "memory")
#define CP_WAIT0()  asm volatile("cp.async.wait_group 0;" ::: "memory")

// swizzled byte offset of 16B chunk (row, c) inside a 128x32-half tile slot
__device__ __forceinline__ uint32_t swz_off(int row, int c) {
    return (uint32_t)(row * 64 + ((c ^ ((row >> 1) & 3)) << 4));
}

// ---------------- fp32 -> fp16 bulk convert ----------------------------------
__global__ void cvt_kernel(const float* __restrict__ src, __half* __restrict__ dst, int n8) {
    int i = blockIdx.x * blockDim.x + threadIdx.x;
    if (i >= n8) return;
    const float4* s = (const float4*)src + 2 * (size_t)i;
    float4 a = s[0], b = s[1];
    __half2 h0 = __floats2half2_rn(a.x, a.y), h1 = __floats2half2_rn(a.z, a.w);
    __half2 h2 = __floats2half2_rn(b.x, b.y), h3 = __floats2half2_rn(b.z, b.w);
    ((uint4*)dst)[i] = make_uint4(*(uint32_t*)&h0, *(uint32_t*)&h1,
                                  *(uint32_t*)&h2, *(uint32_t*)&h3);
}

// ---------------- small kernels (unchanged logic) ----------------------------
__global__ void init_kernel() {
    int t = threadIdx.x;
    if (t < NEXP) g_counts[t] = 0;
}

__global__ void gate_kernel(const float* __restrict__ x,
                            const float* __restrict__ Wg,
                            const float* __restrict__ bg) {
    __shared__ float wgs[NEXP * DMODEL];
    int tid = threadIdx.x;
    for (int i = tid; i < NEXP * DMODEL; i += 256) wgs[i] = Wg[i];
    __syncthreads();
    int w = tid >> 5, l = tid & 31;
    int t = blockIdx.x * 8 + w;
    if (t >= T_TOK) return;
    const float* xr = x + (size_t)t * DMODEL;
    float best = -1e30f; int bi = 0;
    #pragma unroll 1
    for (int e = 0; e < NEXP; e++) {
        float s = 0.f;
        const float* wr = wgs + e * DMODEL;
        for (int k = l; k < DMODEL; k += 32) s += xr[k] * wr[k];
        #pragma unroll
        for (int o = 16; o; o >>= 1) s += __shfl_xor_sync(0xffffffffu, s, o);
        s += bg[e];
        if (s > best) { best = s; bi = e; }   // strict > : first max (jnp.argmax)
    }
    if (l == 0) { g_idx[t] = bi; atomicAdd(&g_counts[bi], 1); }
}

__global__ void scan_kernel() {
    if (threadIdx.x != 0) return;
    int off = 0, nt = 0;
    for (int e = 0; e < NEXP; e++) {
        g_off[e] = off;
        g_cursor[e] = off;
        int c = g_counts[e];
        for (int r = 0; r < c; r += TM) { g_tile_e[nt] = e; g_tile_row[nt] = off + r; nt++; }
        off += c;
    }
    g_off[NEXP] = off;
    for (; nt < MAX_TILES; nt++) g_tile_e[nt] = -1;
}

__global__ void scatter_kernel() {
    int t = blockIdx.x * 256 + threadIdx.x;
    if (t >= T_TOK) return;
    int p = atomicAdd(&g_cursor[g_idx[t]], 1);
    g_perm[p] = t;
}

// ---------------- fp16 mma.sync grouped GEMM, cp.async 4-stage ring ----------
// PHASE 1: hidden[r,:] = fp16(GELU(xh[perm[r]] @ W1h[e]^T + b1[e]))
// PHASE 2: out[perm[r],:] = hidden[r] @ W2h[e]^T + b2[e]
template <int PHASE>
__global__ void __launch_bounds__(256, 2)
mlp_mma(const __half* __restrict__ Ax, const __half* __restrict__ W,
        const float* __restrict__ bias, float* __restrict__ out)
{
    int tile = blockIdx.x;
    int e = g_tile_e[tile];
    if (e < 0) return;
    int row0 = g_tile_row[tile];
    int rend = g_off[e + 1];
    int n0 = blockIdx.y * TN;

    extern __shared__ char sm[];
    float* bias_s = (float*)sm;
    char* ring = sm + RING_OFF;
    uint32_t ring_s = (uint32_t)__cvta_generic_to_shared(ring);
    float* stg = (float*)ring;                 // epilogue staging alias (64 x 136 fp32)

    int tid = threadIdx.x;
    int wid = tid >> 5, lane = tid & 31;
    int wr = wid & 3, wc = wid >> 2;           // warp tile: rows wr*32, cols wc*64
    int lrow = lane >> 2, lcol = lane & 3;
    int lq = lane >> 3, lr = lane & 7;
    int a_row = wr * 32 + (lq & 1) * 8 + lr;   // + mm*16
    int a_cb  = lq >> 1;                       // chunk base, + kk*2
    int b_row = wc * 64 + (lq >> 1) * 8 + lr;  // + np*16
    int b_cb  = lq & 1;

    if (tid < TN) bias_s[tid] = bias[(size_t)e * DMODEL + n0 + tid];

    // loader mapping: thread -> 2 A chunks + 2 B chunks per stage
    // chunk c = tid&3 (16B = 8 halfs), rows tid>>2 and tid>>2 + 64
    int c = tid & 3;
    int r0 = tid >> 2, r1 = r0 + 64;
    const __half* asrc[2]; int asz[2];
    const __half* bsrc[2];
    uint32_t doff[2];
    {
        int rr[2] = {r0, r1};
        #pragma unroll
        for (int j = 0; j < 2; j++) {
            int ar = row0 + rr[j];
            bool v = ar < rend;
            int srow;
            if (PHASE == 1) srow = v ? g_perm[ar] : 0;
            else            srow = v ? ar : 0;
            asrc[j] = Ax + (size_t)srow * DMODEL + c * 8;
            asz[j] = v ? 16 : 0;
            bsrc[j] = W + (size_t)e * DMODEL * DMODEL + (size_t)(n0 + rr[j]) * DMODEL + c * 8;
            doff[j] = swz_off(rr[j], c);
        }
    }

    float acc[2][8][4];
    #pragma unroll
    for (int mm = 0; mm < 2; mm++)
        #pragma unroll
        for (int nn = 0; nn < 8; nn++)
            #pragma unroll
            for (int j = 0; j < 4; j++) acc[mm][nn][j] = 0.f;

    // prologue: stages 0,1,2 in flight
    #pragma unroll
    for (int s = 0; s < 3; s++) {
        uint32_t aslot = ring_s + (s & 3) * SLOT_B;
        uint32_t bslot = ring_s + 4 * SLOT_B + (s & 3) * SLOT_B;
        int ko = s * KSTEP;
        cpa16(aslot + doff[0], asrc[0] + ko, asz[0]);
        cpa16(aslot + doff[1], asrc[1] + ko, asz[1]);
        cpa16(bslot + doff[0], bsrc[0] + ko, 16);
        cpa16(bslot + doff[1], bsrc[1] + ko, 16);
        CP_COMMIT();
    }

    // mainloop
    #pragma unroll 1
    for (int s = 0; s < NSTAGE; s++) {
        CP_WAIT2();
        __syncthreads();
        if (s + 3 < NSTAGE) {
            int sn = s + 3;
            uint32_t aslot = ring_s + (sn & 3) * SLOT_B;
            uint32_t bslot = ring_s + 4 * SLOT_B + (sn & 3) * SLOT_B;
            int ko = sn * KSTEP;
            cpa16(aslot + doff[0], asrc[0] + ko, asz[0]);
            cpa16(aslot + doff[1], asrc[1] + ko, asz[1]);
            cpa16(bslot + doff[0], bsrc[0] + ko, 16);
            cpa16(bslot + doff[1], bsrc[1] + ko, 16);
        }
        CP_COMMIT();   // commit every iter (possibly empty) to keep wait_group math uniform

        uint32_t As = ring_s + (s & 3) * SLOT_B;
        uint32_t Bs = ring_s + 4 * SLOT_B + (s & 3) * SLOT_B;
        #pragma unroll
        for (int kk = 0; kk < 2; kk++) {
            uint32_t af[2][4];
            #pragma unroll
            for (int mm = 0; mm < 2; mm++) {
                int i = a_row + mm * 16;
                ldsm4(af[mm], As + swz_off(i, a_cb + kk * 2));
            }
            uint32_t bf[4][4];
            #pragma unroll
            for (int np = 0; np < 4; np++) {
                int i = b_row + np * 16;
                ldsm4(bf[np], Bs + swz_off(i, b_cb + kk * 2));
            }
            #pragma unroll
            for (int np = 0; np < 4; np++) {
                mma_f16(acc[0][2 * np],     af[0], &bf[np][0]);
                mma_f16(acc[1][2 * np],     af[1], &bf[np][0]);
                mma_f16(acc[0][2 * np + 1], af[0], &bf[np][2]);
                mma_f16(acc[1][2 * np + 1], af[1], &bf[np][2]);
            }
        }
    }
    CP_WAIT0();
    __syncthreads();

    // ---- epilogue: two passes of 64 rows through fp32 staging ----
    #pragma unroll
    for (int p = 0; p < 2; p++) {
        if ((wr >> 1) == p) {
            int rbase = (wr & 1) * 32;
            #pragma unroll
            for (int mm = 0; mm < 2; mm++) {
                #pragma unroll
                for (int nn = 0; nn < 8; nn++) {
                    int col = wc * 64 + nn * 8 + 2 * lcol;
                    int row = rbase + mm * 16 + lrow;
                    float b0 = bias_s[col], b1 = bias_s[col + 1];
                    float v0 = acc[mm][nn][0] + b0, v1 = acc[mm][nn][1] + b1;
                    float v2 = acc[mm][nn][2] + b0, v3 = acc[mm][nn][3] + b1;
                    if (PHASE == 1) {
                        v0 = 0.5f * v0 * (1.0f + erff(v0 * 0.70710678118654752f));
                        v1 = 0.5f * v1 * (1.0f + erff(v1 * 0.70710678118654752f));
                        v2 = 0.5f * v2 * (1.0f + erff(v2 * 0.70710678118654752f));
                        v3 = 0.5f * v3 * (1.0f + erff(v3 * 0.70710678118654752f));
                    }
                    *(float2*)(stg + row * STG_STRIDE + col) = make_float2(v0, v1);
                    *(float2*)(stg + (row + 8) * STG_STRIDE + col) = make_float2(v2, v3);
                }
            }
        }
        __syncthreads();
        // writeout: 4 threads per row, 32 floats each (coalesced)
        {
            int rloc = tid >> 2, q = tid & 3;
            int gr = row0 + p * 64 + rloc;
            if (gr < rend) {
                const float* srow = stg + rloc * STG_STRIDE + q * 32;
                if (PHASE == 1) {
                    __half* dst = g_hidden + (size_t)gr * DMODEL + n0 + q * 32;
                    #pragma unroll
                    for (int j = 0; j < 4; j++) {
                        float4 aa = ((const float4*)srow)[2 * j];
                        float4 bb = ((const float4*)srow)[2 * j + 1];
                        __half2 h0 = __floats2half2_rn(aa.x, aa.y);
                        __half2 h1 = __floats2half2_rn(aa.z, aa.w);
                        __half2 h2 = __floats2half2_rn(bb.x, bb.y);
                        __half2 h3 = __floats2half2_rn(bb.z, bb.w);
                        ((uint4*)dst)[j] = make_uint4(*(uint32_t*)&h0, *(uint32_t*)&h1,
                                                      *(uint32_t*)&h2, *(uint32_t*)&h3);
                    }
                } else {
                    float* dst = out + (size_t)g_perm[gr] * DMODEL + n0 + q * 32;
                    #pragma unroll
                    for (int j = 0; j < 8; j++)
                        ((float4*)dst)[j] = ((const float4*)srow)[j];
                }
            }
        }
        __syncthreads();
    }
}

// ---------------- launch -----------------------------------------------------
extern "C" void kernel_launch(void* const* d_in, const int* in_sizes, int n_in,
                              void* d_out, int out_size) {
    const float* x  = (const float*)d_in[0];
    const float* W1 = (const float*)d_in[1];
    const float* b1 = (const float*)d_in[2];
    const float* W2 = (const float*)d_in[3];
    const float* b2 = (const float*)d_in[4];
    const float* Wg = (const float*)d_in[5];
    const float* bg = (const float*)d_in[6];
    float* out = (float*)d_out;

    cudaFuncSetAttribute(mlp_mma<1>, cudaFuncAttributeMaxDynamicSharedMemorySize, SMEM_BYTES);
    cudaFuncSetAttribute(mlp_mma<2>, cudaFuncAttributeMaxDynamicSharedMemorySize, SMEM_BYTES);

    // resolve device-global addresses host-side (graph-capturable, no sync)
    __half *xh_p, *w1h_p, *w2h_p;
    cudaGetSymbolAddress((void**)&xh_p, g_xh);
    cudaGetSymbolAddress((void**)&w1h_p, g_w1h);
    cudaGetSymbolAddress((void**)&w2h_p, g_w2h);
    __half *hid_p;
    cudaGetSymbolAddress((void**)&hid_p, g_hidden);

    init_kernel<<<1, 32>>>();
    gate_kernel<<<(T_TOK + 7) / 8, 256>>>(x, Wg, bg);
    scan_kernel<<<1, 1>>>();
    scatter_kernel<<<(T_TOK + 255) / 256, 256>>>();

    int nW8 = NEXP * DMODEL * DMODEL / 8;          // 1,179,648
    int nX8 = T_TOK * DMODEL / 8;                  // 605,184
    cvt_kernel<<<(nW8 + 255) / 256, 256>>>(W1, w1h_p, nW8);
    cvt_kernel<<<(nW8 + 255) / 256, 256>>>(W2, w2h_p, nW8);
    cvt_kernel<<<(nX8 + 255) / 256, 256>>>(x, xh_p, nX8);

    dim3 g(MAX_TILES, DMODEL / TN);
    mlp_mma<1><<<g, 256, SMEM_BYTES>>>(xh_p, w1h_p, b1, nullptr);
    mlp_mma<2><<<g, 256, SMEM_BYTES>>>(hid_p, w2h_p, b2, out);
}